// round 15
// baseline (speedup 1.0000x reference)
#include <cuda_runtime.h>
#include <cuda_bf16.h>
#include <cstdint>
#include <math.h>

// Problem constants
#define Bb 4
#define Cc 512
#define NN_ 2048
#define Hh 8
#define Dd 64
#define BH (Bb*Hh)
#define BCN (Bb*Cc*NN_)

// Scratch
__device__ __nv_bfloat16 g_qb[BCN];
__device__ __nv_bfloat16 g_kb[BCN];
__device__ __nv_bfloat16 g_vb[BCN];
__device__ float g_att[BCN];
__device__ float g_msg[BCN];
__device__ float g_h[2*BCN];

// Pre-split weights (bf16)
__device__ __nv_bfloat16 g_wqh[Cc*Cc];
__device__ __nv_bfloat16 g_wkh[Cc*Cc];
__device__ __nv_bfloat16 g_wvh[Cc*Cc];
__device__ __nv_bfloat16 g_wmh[Cc*Cc];
__device__ __nv_bfloat16 g_w1h[4*Cc*Cc];
__device__ __nv_bfloat16 g_w1l[4*Cc*Cc];
__device__ __nv_bfloat16 g_w2h[2*Cc*Cc];
__device__ __nv_bfloat16 g_w2l[2*Cc*Cc];

// ===========================================================================
// Warp-level MMA helpers
// ===========================================================================
__device__ __forceinline__ uint32_t smem_u32(const void* p){
    uint32_t a;
    asm("{ .reg .u64 t; cvta.to.shared.u64 t, %1; cvt.u32.u64 %0, t; }" : "=r"(a) : "l"(p));
    return a;
}
__device__ __forceinline__ void ldsm_x4(uint32_t addr, uint32_t* r){
    asm volatile("ldmatrix.sync.aligned.m8n8.x4.shared.b16 {%0,%1,%2,%3}, [%4];"
        : "=r"(r[0]), "=r"(r[1]), "=r"(r[2]), "=r"(r[3]) : "r"(addr));
}
__device__ __forceinline__ void ldsm_x4t(uint32_t addr, uint32_t* r){
    asm volatile("ldmatrix.sync.aligned.m8n8.x4.trans.shared.b16 {%0,%1,%2,%3}, [%4];"
        : "=r"(r[0]), "=r"(r[1]), "=r"(r[2]), "=r"(r[3]) : "r"(addr));
}
__device__ __forceinline__ void ldsm_x2t(uint32_t addr, uint32_t* r){
    asm volatile("ldmatrix.sync.aligned.m8n8.x2.trans.shared.b16 {%0,%1}, [%2];"
        : "=r"(r[0]), "=r"(r[1]) : "r"(addr));
}
__device__ __forceinline__ void mma16816(float* c, const uint32_t* a, const uint32_t* b){
    asm volatile("mma.sync.aligned.m16n8k16.row.col.f32.bf16.bf16.f32 "
        "{%0,%1,%2,%3}, {%4,%5,%6,%7}, {%8,%9}, {%0,%1,%2,%3};"
        : "+f"(c[0]), "+f"(c[1]), "+f"(c[2]), "+f"(c[3])
        : "r"(a[0]), "r"(a[1]), "r"(a[2]), "r"(a[3]), "r"(b[0]), "r"(b[1]));
}
__device__ __forceinline__ void cp16(uint32_t dst, const void* src){
    asm volatile("cp.async.ca.shared.global [%0], [%1], 16;" :: "r"(dst), "l"(src));
}
#define CP_COMMIT() asm volatile("cp.async.commit_group;" ::: "memory")
#define CP_WAIT0()  asm volatile("cp.async.wait_group 0;" ::: "memory")

__device__ __forceinline__ void split4(float4 v, uint2& H, uint2& L)
{
    __nv_bfloat16 h0 = __float2bfloat16(v.x);
    __nv_bfloat16 h1 = __float2bfloat16(v.y);
    __nv_bfloat16 h2 = __float2bfloat16(v.z);
    __nv_bfloat16 h3 = __float2bfloat16(v.w);
    __nv_bfloat16 l0 = __float2bfloat16(v.x - __bfloat162float(h0));
    __nv_bfloat16 l1 = __float2bfloat16(v.y - __bfloat162float(h1));
    __nv_bfloat16 l2 = __float2bfloat16(v.z - __bfloat162float(h2));
    __nv_bfloat16 l3 = __float2bfloat16(v.w - __bfloat162float(h3));
    H.x = (uint32_t)__bfloat16_as_ushort(h0) | ((uint32_t)__bfloat16_as_ushort(h1) << 16);
    H.y = (uint32_t)__bfloat16_as_ushort(h2) | ((uint32_t)__bfloat16_as_ushort(h3) << 16);
    L.x = (uint32_t)__bfloat16_as_ushort(l0) | ((uint32_t)__bfloat16_as_ushort(l1) << 16);
    L.y = (uint32_t)__bfloat16_as_ushort(l2) | ((uint32_t)__bfloat16_as_ushort(l3) << 16);
}

__device__ __forceinline__ void hi4(float4 v, uint2& H)
{
    __nv_bfloat16 h0 = __float2bfloat16(v.x);
    __nv_bfloat16 h1 = __float2bfloat16(v.y);
    __nv_bfloat16 h2 = __float2bfloat16(v.z);
    __nv_bfloat16 h3 = __float2bfloat16(v.w);
    H.x = (uint32_t)__bfloat16_as_ushort(h0) | ((uint32_t)__bfloat16_as_ushort(h1) << 16);
    H.y = (uint32_t)__bfloat16_as_ushort(h2) | ((uint32_t)__bfloat16_as_ushort(h3) << 16);
}

__device__ __forceinline__ uint32_t packbf(float a, float b){
    __nv_bfloat162 t = __floats2bfloat162_rn(a, b);
    return *(uint32_t*)&t;
}

// ===========================================================================
// Weight pre-split: fp32 -> bf16 hi (+ optional lo)
// ===========================================================================
__global__ void wsplit(const float* __restrict__ W, __nv_bfloat16* __restrict__ H,
                       __nv_bfloat16* __restrict__ L, int n4)
{
    int i = blockIdx.x * blockDim.x + threadIdx.x;
    if (i < n4) {
        float4 v = ((const float4*)W)[i];
        uint2 Hv, Lv; split4(v, Hv, Lv);
        *(uint2*)(H + 4*(size_t)i) = Hv;
        if (L) *(uint2*)(L + 4*(size_t)i) = Lv;
    }
}

// ===========================================================================
// MMA GEMM: 128m x 64n, 2 CTAs/SM, prefetch pipeline, fused-concat option.
// Weights come PRE-SPLIT as bf16 (Wh always; Wl iff TERMS==3).
// TERMS=3: AhBh + AhBl + AlBh ; TERMS=2: AhBh + AhBl ; TERMS=1: AhBh.
// OUTBF=1 -> write bf16 output.
// ===========================================================================
#define A_STRIDE 40
#define BS 72

template<int TERMS, int OUTBF>
__global__ void __launch_bounds__(256, 2)
mma_gemm(const __nv_bfloat16* __restrict__ Wh, const __nv_bfloat16* __restrict__ Wl,
         const float* __restrict__ bias,
         const float* __restrict__ X1, const float* __restrict__ X2, int K1,
         const float* __restrict__ res, void* __restrict__ Yv,
         int M, int K, int Nc)
{
    __shared__ __align__(16) __nv_bfloat16 sAh[128 * A_STRIDE];
    __shared__ __align__(16) __nv_bfloat16 sAl[TERMS == 3 ? 128 * A_STRIDE : 8];
    __shared__ __align__(16) __nv_bfloat16 sBh[32 * BS];
    __shared__ __align__(16) __nv_bfloat16 sBl[TERMS >= 2 ? 32 * BS : 8];

    const int t = threadIdx.x;
    const int lane = t & 31;
    const int wid = t >> 5;
    const int wm = wid & 3;
    const int wn = wid >> 2;

    const int b  = blockIdx.z;
    const int m0 = blockIdx.y * 128;
    const int n0 = blockIdx.x * 64;
    const float* X1b = X1 + (size_t)b * K1 * Nc;
    const float* X2b = X2 ? X2 + (size_t)b * (K - K1) * Nc : (const float*)0;

    const uint32_t ah_base = smem_u32(sAh);
    const uint32_t al_base = smem_u32(sAl);
    const uint32_t bh_base = smem_u32(sBh);
    const uint32_t bl_base = smem_u32(sBl);

    float acc[2][4][4] = {};

    const int a_row = (lane & 15);
    const int a_koff = (lane & 16) ? 8 : 0;
    const int b_row = (lane & 15);

    // A staging coords: row = t&127, k-half = (t>>7)*16
    const int aw_m = t & 127;
    const int aw_k = (t >> 7) << 4;
    const int bw_k = (t >> 4);
    const int bw_n = (t & 15) << 2;

    uint4 wrh[2], wrl[2];
    float4 xr[2];

    #pragma unroll
    for (int j = 0; j < 2; j++)
        wrh[j] = *(const uint4*)(Wh + (size_t)(m0 + aw_m) * K + aw_k + 8*j);
    if (TERMS == 3)
        #pragma unroll
        for (int j = 0; j < 2; j++)
            wrl[j] = *(const uint4*)(Wl + (size_t)(m0 + aw_m) * K + aw_k + 8*j);
    #pragma unroll
    for (int p = 0; p < 2; p++)
        xr[p] = *(const float4*)(X1b + (size_t)(bw_k + (p << 4)) * Nc + n0 + bw_n);

    const int nchunks = K >> 5;
    for (int ch = 0; ch < nchunks; ch++) {
        __syncthreads();

        #pragma unroll
        for (int j = 0; j < 2; j++)
            *(uint4*)&sAh[aw_m * A_STRIDE + aw_k + 8*j] = wrh[j];
        if (TERMS == 3)
            #pragma unroll
            for (int j = 0; j < 2; j++)
                *(uint4*)&sAl[aw_m * A_STRIDE + aw_k + 8*j] = wrl[j];
        #pragma unroll
        for (int p = 0; p < 2; p++) {
            if (TERMS >= 2) {
                uint2 Hv, Lv; split4(xr[p], Hv, Lv);
                *(uint2*)&sBh[(bw_k + (p << 4)) * BS + bw_n] = Hv;
                *(uint2*)&sBl[(bw_k + (p << 4)) * BS + bw_n] = Lv;
            } else {
                uint2 Hv; hi4(xr[p], Hv);
                *(uint2*)&sBh[(bw_k + (p << 4)) * BS + bw_n] = Hv;
            }
        }
        __syncthreads();

        if (ch + 1 < nchunks) {
            const int k0 = (ch + 1) << 5;
            #pragma unroll
            for (int j = 0; j < 2; j++)
                wrh[j] = *(const uint4*)(Wh + (size_t)(m0 + aw_m) * K + k0 + aw_k + 8*j);
            if (TERMS == 3)
                #pragma unroll
                for (int j = 0; j < 2; j++)
                    wrl[j] = *(const uint4*)(Wl + (size_t)(m0 + aw_m) * K + k0 + aw_k + 8*j);
            const float* base; int krel;
            if (k0 < K1) { base = X1b; krel = k0; }
            else         { base = X2b; krel = k0 - K1; }
            #pragma unroll
            for (int p = 0; p < 2; p++)
                xr[p] = *(const float4*)(base + (size_t)(krel + bw_k + (p << 4)) * Nc + n0 + bw_n);
        }

        #pragma unroll
        for (int ks = 0; ks < 2; ks++) {
            const int kk = ks << 4;
            uint32_t ah[2][4], al[2][4], bh[4][2], bl[4][2];
            #pragma unroll
            for (int mf = 0; mf < 2; mf++) {
                const int row = wm * 32 + mf * 16 + a_row;
                const uint32_t off = (uint32_t)(row * A_STRIDE + kk + a_koff) * 2u;
                ldsm_x4(ah_base + off, ah[mf]);
                if (TERMS == 3) ldsm_x4(al_base + off, al[mf]);
            }
            #pragma unroll
            for (int nf = 0; nf < 4; nf++) {
                const int nb = wn * 32 + nf * 8;
                const uint32_t off = (uint32_t)((kk + b_row) * BS + nb) * 2u;
                ldsm_x2t(bh_base + off, bh[nf]);
                if (TERMS >= 2) ldsm_x2t(bl_base + off, bl[nf]);
            }
            #pragma unroll
            for (int mf = 0; mf < 2; mf++)
                #pragma unroll
                for (int nf = 0; nf < 4; nf++) {
                    mma16816(acc[mf][nf], ah[mf], bh[nf]);
                    if (TERMS >= 2) mma16816(acc[mf][nf], ah[mf], bl[nf]);
                    if (TERMS == 3) mma16816(acc[mf][nf], al[mf], bh[nf]);
                }
        }
    }

    const int r = lane >> 2;
    const int c = (lane & 3) << 1;

    #pragma unroll
    for (int mf = 0; mf < 2; mf++) {
        const int gm = m0 + wm * 32 + mf * 16 + r;
        const float bv0 = bias[gm];
        const float bv1 = bias[gm + 8];
        #pragma unroll
        for (int nf = 0; nf < 4; nf++) {
            const int gn = n0 + wn * 32 + nf * 8 + c;
            const size_t i0 = (size_t)gm * Nc + gn;
            const size_t i1 = (size_t)(gm + 8) * Nc + gn;
            if (OUTBF) {
                __nv_bfloat16* Yb = (__nv_bfloat16*)Yv + (size_t)b * M * Nc;
                *(uint32_t*)(Yb + i0) = packbf(acc[mf][nf][0] + bv0, acc[mf][nf][1] + bv0);
                *(uint32_t*)(Yb + i1) = packbf(acc[mf][nf][2] + bv1, acc[mf][nf][3] + bv1);
            } else {
                float* Yb = (float*)Yv + (size_t)b * M * Nc;
                const float* Rb = res ? res + (size_t)b * M * Nc : (const float*)0;
                float2 v0 = make_float2(acc[mf][nf][0] + bv0, acc[mf][nf][1] + bv0);
                float2 v1 = make_float2(acc[mf][nf][2] + bv1, acc[mf][nf][3] + bv1);
                if (Rb) {
                    float2 r0 = *(const float2*)(Rb + i0);
                    float2 r1 = *(const float2*)(Rb + i1);
                    v0.x += r0.x; v0.y += r0.y;
                    v1.x += r1.x; v1.y += r1.y;
                }
                *(float2*)(Yb + i0) = v0;
                *(float2*)(Yb + i1) = v1;
            }
        }
    }
}

// ===========================================================================
// Flash attention (unchanged from R11): bf16 inputs, cp.async KV pipeline.
// ===========================================================================
#define FA_SMEM (17408 + 2*18432)

__global__ void __launch_bounds__(256, 2)
flash_attn(const __nv_bfloat16* __restrict__ q, const __nv_bfloat16* __restrict__ k,
           const __nv_bfloat16* __restrict__ v, float* __restrict__ out)
{
    extern __shared__ __align__(16) char sbuf[];
    const int t = threadIdx.x, lane = t & 31, w = t >> 5;
    const int bh = blockIdx.y, b = bh >> 3, h = bh & 7;
    const int n0 = blockIdx.x * 128;

    const __nv_bfloat16* qb = q + (size_t)b * Cc * NN_ + (size_t)h * NN_;
    const __nv_bfloat16* kb = k + (size_t)b * Cc * NN_ + (size_t)h * NN_;
    const __nv_bfloat16* vb = v + (size_t)b * Cc * NN_ + (size_t)h * NN_;

    __nv_bfloat16* sQh = (__nv_bfloat16*)sbuf;                // [64][136]
    const uint32_t qh_b  = smem_u32(sQh);
    const uint32_t kv0_b = qh_b + 17408;
    const int c_row0 = t >> 3,         c_c0 = (t & 7) << 3;
    const int c_row1 = (t + 256) >> 3, c_c1 = ((t + 256) & 7) << 3;

    {
        const uint32_t kd = kv0_b, vd = kv0_b + 9216;
        cp16(kd + (uint32_t)(c_row0*72 + c_c0)*2u, kb + ((size_t)c_row0 << 14) + c_c0);
        cp16(kd + (uint32_t)(c_row1*72 + c_c1)*2u, kb + ((size_t)c_row1 << 14) + c_c1);
        cp16(vd + (uint32_t)(c_row0*72 + c_c0)*2u, vb + ((size_t)c_row0 << 14) + c_c0);
        cp16(vd + (uint32_t)(c_row1*72 + c_c1)*2u, vb + ((size_t)c_row1 << 14) + c_c1);
        CP_COMMIT();
    }

    {
        const int d = t >> 2, c0 = (t & 3) << 5;
        #pragma unroll
        for (int j = 0; j < 4; j++)
            *(uint4*)&sQh[d*136 + c0 + j*8] = *(const uint4*)(qb + ((size_t)d << 14) + n0 + c0 + j*8);
    }

    float of[8][4] = {};
    float l0 = 0.f, l1 = 0.f;

    const int q_row_off = ((lane>>4)&1)*8 + (lane&7);
    const int q_col = w*16 + ((lane>>3)&1)*8;
    const int brow = ((lane>>3)&1)*8 + (lane&7);
    const int bcol8 = ((lane>>4)&1)*8;
    const int v_row = ((lane>>4)&1)*8 + (lane&7);
    const int v_col = ((lane>>3)&1)*8;

    __syncthreads();

    for (int it = 0; it < NN_/64; it++) {
        const uint32_t cur_b = kv0_b + (uint32_t)(it & 1) * 18432u;
        CP_WAIT0();
        __syncthreads();

        if (it + 1 < NN_/64) {
            const int nx = (it + 1) << 6;
            const uint32_t nb = kv0_b + (uint32_t)((it + 1) & 1) * 18432u;
            const uint32_t kd = nb, vd = nb + 9216;
            cp16(kd + (uint32_t)(c_row0*72 + c_c0)*2u, kb + ((size_t)c_row0 << 14) + nx + c_c0);
            cp16(kd + (uint32_t)(c_row1*72 + c_c1)*2u, kb + ((size_t)c_row1 << 14) + nx + c_c1);
            cp16(vd + (uint32_t)(c_row0*72 + c_c0)*2u, vb + ((size_t)c_row0 << 14) + nx + c_c0);
            cp16(vd + (uint32_t)(c_row1*72 + c_c1)*2u, vb + ((size_t)c_row1 << 14) + nx + c_c1);
            CP_COMMIT();
        }

        const uint32_t kh_b = cur_b;
        const uint32_t vh_b = cur_b + 9216;

        float sf[8][4];
        #pragma unroll
        for (int f = 0; f < 8; f++) { sf[f][0]=0.f; sf[f][1]=0.f; sf[f][2]=0.f; sf[f][3]=0.f; }

        #pragma unroll
        for (int kk = 0; kk < 4; kk++) {
            uint32_t qf[4];
            ldsm_x4t(qh_b + (uint32_t)((kk*16 + q_row_off)*136 + q_col)*2u, qf);
            #pragma unroll
            for (int mp = 0; mp < 4; mp++) {
                const uint32_t koff = (uint32_t)((kk*16 + brow)*72 + mp*16 + bcol8)*2u;
                uint32_t bh4[4];
                ldsm_x4t(kh_b + koff, bh4);
                mma16816(sf[2*mp],   qf, bh4);
                mma16816(sf[2*mp+1], qf, bh4+2);
            }
        }

        float rs0 = 0.f, rs1 = 0.f;
        uint32_t ah4[4][4];
        #pragma unroll
        for (int f = 0; f < 8; f++) {
            float p0 = __expf(0.125f*sf[f][0]);
            float p1 = __expf(0.125f*sf[f][1]);
            float p2 = __expf(0.125f*sf[f][2]);
            float p3 = __expf(0.125f*sf[f][3]);
            rs0 += p0 + p1; rs1 += p2 + p3;
            const int mp = f >> 1, rg = (f & 1) << 1;
            ah4[mp][rg]   = packbf(p0, p1);
            ah4[mp][rg+1] = packbf(p2, p3);
        }
        rs0 += __shfl_xor_sync(0xffffffffu, rs0, 1);
        rs0 += __shfl_xor_sync(0xffffffffu, rs0, 2);
        rs1 += __shfl_xor_sync(0xffffffffu, rs1, 1);
        rs1 += __shfl_xor_sync(0xffffffffu, rs1, 2);
        l0 += rs0;
        l1 += rs1;

        #pragma unroll
        for (int mp = 0; mp < 4; mp++) {
            #pragma unroll
            for (int dp = 0; dp < 4; dp++) {
                const uint32_t voff = (uint32_t)((dp*16 + v_row)*72 + mp*16 + v_col)*2u;
                uint32_t vh4[4];
                ldsm_x4(vh_b + voff, vh4);
                mma16816(of[2*dp],   ah4[mp], vh4);
                mma16816(of[2*dp+1], ah4[mp], vh4+2);
            }
        }
    }

    const float inv0 = 1.f / l0;
    const float inv1 = 1.f / l1;
    float* sO = (float*)(sbuf + 17408);
    float* ob = out + (size_t)b * Cc * NN_ + (size_t)h * NN_;
    __syncthreads();

    #pragma unroll
    for (int half = 0; half < 2; half++) {
        {
            const int r0 = w*16 + (lane >> 2);
            const int dvb = (lane & 3) << 1;
            #pragma unroll
            for (int fl = 0; fl < 4; fl++) {
                const int f = half*4 + fl;
                const int dv = fl*8 + dvb;
                sO[dv*132 + r0]       = of[f][0] * inv0;
                sO[(dv+1)*132 + r0]   = of[f][1] * inv0;
                sO[dv*132 + r0 + 8]   = of[f][2] * inv1;
                sO[(dv+1)*132 + r0+8] = of[f][3] * inv1;
            }
        }
        __syncthreads();
        {
            const int dvl = t >> 3;
            const int nq = (t & 7) << 4;
            #pragma unroll
            for (int j = 0; j < 4; j++) {
                *(float4*)(ob + ((size_t)(half*32 + dvl) << 14) + n0 + nq + 4*j)
                    = *(float4*)&sO[dvl*132 + nq + 4*j];
            }
        }
        __syncthreads();
    }
}

// ===========================================================================
// instance-norm + relu
// ===========================================================================
__global__ void inorm_relu(float* __restrict__ X)
{
    float* row = X + (size_t)blockIdx.x * NN_;
    const int tid = threadIdx.x;
    __shared__ float redA[8], redB[8];

    float v[8];
    float s = 0.f, s2 = 0.f;
    #pragma unroll
    for (int i = 0; i < 8; i++) { v[i] = row[tid + 256*i]; s += v[i]; s2 += v[i]*v[i]; }

    #pragma unroll
    for (int o = 16; o > 0; o >>= 1) {
        s  += __shfl_xor_sync(0xffffffffu, s, o);
        s2 += __shfl_xor_sync(0xffffffffu, s2, o);
    }
    if ((tid & 31) == 0) { redA[tid >> 5] = s; redB[tid >> 5] = s2; }
    __syncthreads();
    if (tid < 8) {
        float a = redA[tid], b = redB[tid];
        #pragma unroll
        for (int o = 4; o > 0; o >>= 1) {
            a += __shfl_xor_sync(0xffu, a, o);
            b += __shfl_xor_sync(0xffu, b, o);
        }
        if (tid == 0) { redA[0] = a; redB[0] = b; }
    }
    __syncthreads();
    const float mean = redA[0] * (1.f / NN_);
    const float var  = redB[0] * (1.f / NN_) - mean * mean;
    const float inv  = rsqrtf(var + 1e-5f);

    #pragma unroll
    for (int i = 0; i < 8; i++) {
        float y = (v[i] - mean) * inv;
        row[tid + 256*i] = y > 0.f ? y : 0.f;
    }
}

// ===========================================================================
// Host side
// ===========================================================================
template<int TERMS, int OUTBF>
static void launch_gemm(const __nv_bfloat16* Wh, const __nv_bfloat16* Wl,
                        const float* bias,
                        const float* X1, const float* X2, int K1,
                        const float* res, void* Y, int M, int K)
{
    dim3 g(NN_ / 64, M / 128, Bb);
    mma_gemm<TERMS, OUTBF><<<g, 256>>>(Wh, Wl, bias, X1, X2, K1, res, Y, M, K, NN_);
}

struct WPtrs {
    __nv_bfloat16 *qh, *kh, *vh, *mh, *w1h, *w1l, *w2h, *w2l;
};

static void run_pass(const float* A, const float* KV, float* dst, const WPtrs& wp,
                     const float* bq, const float* bk, const float* bv, const float* bm,
                     const float* b1, const float* b2,
                     __nv_bfloat16* q, __nv_bfloat16* k, __nv_bfloat16* v,
                     float* att, float* msg, float* hb)
{
    launch_gemm<1,1>(wp.qh, nullptr, bq, A,  nullptr, Cc, nullptr, q, Cc, Cc);
    launch_gemm<1,1>(wp.kh, nullptr, bk, KV, nullptr, Cc, nullptr, k, Cc, Cc);
    launch_gemm<2,1>(wp.vh, nullptr, bv, KV, nullptr, Cc, nullptr, v, Cc, Cc);

    flash_attn<<<dim3(NN_/128, BH), 256, FA_SMEM>>>(q, k, v, att);

    launch_gemm<2,0>(wp.mh, nullptr, bm, att, nullptr, Cc, nullptr, msg, Cc, Cc);

    launch_gemm<3,0>(wp.w1h, wp.w1l, b1, A, msg, Cc, nullptr, hb, 2*Cc, 2*Cc);
    inorm_relu<<<Bb * 2 * Cc, 256>>>(hb);
    launch_gemm<3,0>(wp.w2h, wp.w2l, b2, hb, nullptr, 2*Cc, A, dst, Cc, 2*Cc);
}

extern "C" void kernel_launch(void* const* d_in, const int* in_sizes, int n_in,
                              void* d_out, int out_size)
{
    const float* src = (const float*)d_in[0];
    const float* tgt = (const float*)d_in[1];
    const float* Wq = (const float*)d_in[2];   const float* bq = (const float*)d_in[3];
    const float* Wk = (const float*)d_in[4];   const float* bk = (const float*)d_in[5];
    const float* Wv = (const float*)d_in[6];   const float* bv = (const float*)d_in[7];
    const float* Wm = (const float*)d_in[8];   const float* bm = (const float*)d_in[9];
    const float* W1 = (const float*)d_in[10];  const float* b1 = (const float*)d_in[11];
    const float* W2 = (const float*)d_in[12];  const float* b2 = (const float*)d_in[13];

    float* out = (float*)d_out;
    float* out_src = out;
    float* out_tgt = out + (size_t)BCN;

    static int s_init = 0;
    if (!s_init) {
        cudaFuncSetAttribute(flash_attn, cudaFuncAttributeMaxDynamicSharedMemorySize, FA_SMEM);
        s_init = 1;
    }

    __nv_bfloat16 *q, *k, *v;
    float *att, *msg, *hb;
    cudaGetSymbolAddress((void**)&q,   g_qb);
    cudaGetSymbolAddress((void**)&k,   g_kb);
    cudaGetSymbolAddress((void**)&v,   g_vb);
    cudaGetSymbolAddress((void**)&att, g_att);
    cudaGetSymbolAddress((void**)&msg, g_msg);
    cudaGetSymbolAddress((void**)&hb,  g_h);

    WPtrs wp;
    cudaGetSymbolAddress((void**)&wp.qh,  g_wqh);
    cudaGetSymbolAddress((void**)&wp.kh,  g_wkh);
    cudaGetSymbolAddress((void**)&wp.vh,  g_wvh);
    cudaGetSymbolAddress((void**)&wp.mh,  g_wmh);
    cudaGetSymbolAddress((void**)&wp.w1h, g_w1h);
    cudaGetSymbolAddress((void**)&wp.w1l, g_w1l);
    cudaGetSymbolAddress((void**)&wp.w2h, g_w2h);
    cudaGetSymbolAddress((void**)&wp.w2l, g_w2l);

    // Pre-split weights (hi for all; lo for the TERMS=3 pair)
    {
        const int n512 = Cc*Cc/4;      // 65536 float4
        wsplit<<<n512/256, 256>>>(Wq, wp.qh, nullptr, n512);
        wsplit<<<n512/256, 256>>>(Wk, wp.kh, nullptr, n512);
        wsplit<<<n512/256, 256>>>(Wv, wp.vh, nullptr, n512);
        wsplit<<<n512/256, 256>>>(Wm, wp.mh, nullptr, n512);
        wsplit<<<4*n512/256, 256>>>(W1, wp.w1h, wp.w1l, 4*n512);
        wsplit<<<2*n512/256, 256>>>(W2, wp.w2h, wp.w2l, 2*n512);
    }

    run_pass(src, tgt, out_src, wp, bq, bk, bv, bm, b1, b2, q, k, v, att, msg, hb);
    run_pass(tgt, out_src, out_tgt, wp, bq, bk, bv, bm, b1, b2, q, k, v, att, msg, hb);
}

// round 16
// speedup vs baseline: 1.2556x; 1.2556x over previous
#include <cuda_runtime.h>
#include <cuda_bf16.h>
#include <cstdint>
#include <math.h>

// Problem constants
#define Bb 4
#define Cc 512
#define NN_ 2048
#define Hh 8
#define Dd 64
#define BH (Bb*Hh)
#define BCN (Bb*Cc*NN_)

// Scratch
__device__ __nv_bfloat16 g_qb[BCN];
__device__ __nv_bfloat16 g_kb[BCN];
__device__ __nv_bfloat16 g_vb[BCN];
__device__ float g_att[BCN];
__device__ float g_msg[BCN];
__device__ float g_h[2*BCN];

// Pre-split weights (bf16)
__device__ __nv_bfloat16 g_wqh[Cc*Cc];
__device__ __nv_bfloat16 g_wkh[Cc*Cc];
__device__ __nv_bfloat16 g_wvh[Cc*Cc];
__device__ __nv_bfloat16 g_wmh[Cc*Cc];
__device__ __nv_bfloat16 g_w1h[4*Cc*Cc];
__device__ __nv_bfloat16 g_w1l[4*Cc*Cc];
__device__ __nv_bfloat16 g_w2h[2*Cc*Cc];
__device__ __nv_bfloat16 g_w2l[2*Cc*Cc];

// ===========================================================================
// Warp-level MMA helpers
// ===========================================================================
__device__ __forceinline__ uint32_t smem_u32(const void* p){
    uint32_t a;
    asm("{ .reg .u64 t; cvta.to.shared.u64 t, %1; cvt.u32.u64 %0, t; }" : "=r"(a) : "l"(p));
    return a;
}
__device__ __forceinline__ void ldsm_x4(uint32_t addr, uint32_t* r){
    asm volatile("ldmatrix.sync.aligned.m8n8.x4.shared.b16 {%0,%1,%2,%3}, [%4];"
        : "=r"(r[0]), "=r"(r[1]), "=r"(r[2]), "=r"(r[3]) : "r"(addr));
}
__device__ __forceinline__ void ldsm_x4t(uint32_t addr, uint32_t* r){
    asm volatile("ldmatrix.sync.aligned.m8n8.x4.trans.shared.b16 {%0,%1,%2,%3}, [%4];"
        : "=r"(r[0]), "=r"(r[1]), "=r"(r[2]), "=r"(r[3]) : "r"(addr));
}
__device__ __forceinline__ void ldsm_x2t(uint32_t addr, uint32_t* r){
    asm volatile("ldmatrix.sync.aligned.m8n8.x2.trans.shared.b16 {%0,%1}, [%2];"
        : "=r"(r[0]), "=r"(r[1]) : "r"(addr));
}
__device__ __forceinline__ void mma16816(float* c, const uint32_t* a, const uint32_t* b){
    asm volatile("mma.sync.aligned.m16n8k16.row.col.f32.bf16.bf16.f32 "
        "{%0,%1,%2,%3}, {%4,%5,%6,%7}, {%8,%9}, {%0,%1,%2,%3};"
        : "+f"(c[0]), "+f"(c[1]), "+f"(c[2]), "+f"(c[3])
        : "r"(a[0]), "r"(a[1]), "r"(a[2]), "r"(a[3]), "r"(b[0]), "r"(b[1]));
}
__device__ __forceinline__ void cp16(uint32_t dst, const void* src){
    asm volatile("cp.async.ca.shared.global [%0], [%1], 16;" :: "r"(dst), "l"(src));
}
#define CP_COMMIT() asm volatile("cp.async.commit_group;" ::: "memory")
#define CP_WAIT0()  asm volatile("cp.async.wait_group 0;" ::: "memory")

__device__ __forceinline__ void split4(float4 v, uint2& H, uint2& L)
{
    __nv_bfloat16 h0 = __float2bfloat16(v.x);
    __nv_bfloat16 h1 = __float2bfloat16(v.y);
    __nv_bfloat16 h2 = __float2bfloat16(v.z);
    __nv_bfloat16 h3 = __float2bfloat16(v.w);
    __nv_bfloat16 l0 = __float2bfloat16(v.x - __bfloat162float(h0));
    __nv_bfloat16 l1 = __float2bfloat16(v.y - __bfloat162float(h1));
    __nv_bfloat16 l2 = __float2bfloat16(v.z - __bfloat162float(h2));
    __nv_bfloat16 l3 = __float2bfloat16(v.w - __bfloat162float(h3));
    H.x = (uint32_t)__bfloat16_as_ushort(h0) | ((uint32_t)__bfloat16_as_ushort(h1) << 16);
    H.y = (uint32_t)__bfloat16_as_ushort(h2) | ((uint32_t)__bfloat16_as_ushort(h3) << 16);
    L.x = (uint32_t)__bfloat16_as_ushort(l0) | ((uint32_t)__bfloat16_as_ushort(l1) << 16);
    L.y = (uint32_t)__bfloat16_as_ushort(l2) | ((uint32_t)__bfloat16_as_ushort(l3) << 16);
}

__device__ __forceinline__ void hi4(float4 v, uint2& H)
{
    __nv_bfloat16 h0 = __float2bfloat16(v.x);
    __nv_bfloat16 h1 = __float2bfloat16(v.y);
    __nv_bfloat16 h2 = __float2bfloat16(v.z);
    __nv_bfloat16 h3 = __float2bfloat16(v.w);
    H.x = (uint32_t)__bfloat16_as_ushort(h0) | ((uint32_t)__bfloat16_as_ushort(h1) << 16);
    H.y = (uint32_t)__bfloat16_as_ushort(h2) | ((uint32_t)__bfloat16_as_ushort(h3) << 16);
}

__device__ __forceinline__ uint32_t packbf(float a, float b){
    __nv_bfloat162 t = __floats2bfloat162_rn(a, b);
    return *(uint32_t*)&t;
}

// ===========================================================================
// Weight pre-split: fp32 -> bf16 hi (+ optional lo)
// ===========================================================================
__global__ void wsplit(const float* __restrict__ W, __nv_bfloat16* __restrict__ H,
                       __nv_bfloat16* __restrict__ L, int n4)
{
    int i = blockIdx.x * blockDim.x + threadIdx.x;
    if (i < n4) {
        float4 v = ((const float4*)W)[i];
        uint2 Hv, Lv; split4(v, Hv, Lv);
        *(uint2*)(H + 4*(size_t)i) = Hv;
        if (L) *(uint2*)(L + 4*(size_t)i) = Lv;
    }
}

// ===========================================================================
// MMA GEMM: 128m x 64n, 2 CTAs/SM, prefetch pipeline, fused-concat option.
// Weights PRE-SPLIT bf16. A staging uses R11's proven coalesced pattern:
// row = t>>3 (+p*32), col = (t&7)*4 halves (uint2 per thread).
// TERMS=3: AhBh + AhBl + AlBh ; TERMS=2: AhBh + AhBl ; TERMS=1: AhBh.
// ===========================================================================
#define A_STRIDE 40
#define BS 72

template<int TERMS, int OUTBF>
__global__ void __launch_bounds__(256, 2)
mma_gemm(const __nv_bfloat16* __restrict__ Wh, const __nv_bfloat16* __restrict__ Wl,
         const float* __restrict__ bias,
         const float* __restrict__ X1, const float* __restrict__ X2, int K1,
         const float* __restrict__ res, void* __restrict__ Yv,
         int M, int K, int Nc)
{
    __shared__ __align__(16) __nv_bfloat16 sAh[128 * A_STRIDE];
    __shared__ __align__(16) __nv_bfloat16 sAl[TERMS == 3 ? 128 * A_STRIDE : 8];
    __shared__ __align__(16) __nv_bfloat16 sBh[32 * BS];
    __shared__ __align__(16) __nv_bfloat16 sBl[TERMS >= 2 ? 32 * BS : 8];

    const int t = threadIdx.x;
    const int lane = t & 31;
    const int wid = t >> 5;
    const int wm = wid & 3;
    const int wn = wid >> 2;

    const int b  = blockIdx.z;
    const int m0 = blockIdx.y * 128;
    const int n0 = blockIdx.x * 64;
    const float* X1b = X1 + (size_t)b * K1 * Nc;
    const float* X2b = X2 ? X2 + (size_t)b * (K - K1) * Nc : (const float*)0;

    const uint32_t ah_base = smem_u32(sAh);
    const uint32_t al_base = smem_u32(sAl);
    const uint32_t bh_base = smem_u32(sBh);
    const uint32_t bl_base = smem_u32(sBl);

    float acc[2][4][4] = {};

    const int a_row = (lane & 15);
    const int a_koff = (lane & 16) ? 8 : 0;
    const int b_row = (lane & 15);

    // R11-style A staging coords: row = t>>3 (+p*32), col = (t&7)*4 halves
    const int aw_m = (t >> 3);
    const int aw_k = (t & 7) << 2;
    const int bw_k = (t >> 4);
    const int bw_n = (t & 15) << 2;

    uint2 wrh[4], wrl[4];
    float4 xr[2];

    #pragma unroll
    for (int p = 0; p < 4; p++)
        wrh[p] = *(const uint2*)(Wh + (size_t)(m0 + aw_m + (p << 5)) * K + aw_k);
    if (TERMS == 3)
        #pragma unroll
        for (int p = 0; p < 4; p++)
            wrl[p] = *(const uint2*)(Wl + (size_t)(m0 + aw_m + (p << 5)) * K + aw_k);
    #pragma unroll
    for (int p = 0; p < 2; p++)
        xr[p] = *(const float4*)(X1b + (size_t)(bw_k + (p << 4)) * Nc + n0 + bw_n);

    const int nchunks = K >> 5;
    for (int ch = 0; ch < nchunks; ch++) {
        __syncthreads();

        #pragma unroll
        for (int p = 0; p < 4; p++)
            *(uint2*)&sAh[(aw_m + (p << 5)) * A_STRIDE + aw_k] = wrh[p];
        if (TERMS == 3)
            #pragma unroll
            for (int p = 0; p < 4; p++)
                *(uint2*)&sAl[(aw_m + (p << 5)) * A_STRIDE + aw_k] = wrl[p];
        #pragma unroll
        for (int p = 0; p < 2; p++) {
            if (TERMS >= 2) {
                uint2 Hv, Lv; split4(xr[p], Hv, Lv);
                *(uint2*)&sBh[(bw_k + (p << 4)) * BS + bw_n] = Hv;
                *(uint2*)&sBl[(bw_k + (p << 4)) * BS + bw_n] = Lv;
            } else {
                uint2 Hv; hi4(xr[p], Hv);
                *(uint2*)&sBh[(bw_k + (p << 4)) * BS + bw_n] = Hv;
            }
        }
        __syncthreads();

        if (ch + 1 < nchunks) {
            const int k0 = (ch + 1) << 5;
            #pragma unroll
            for (int p = 0; p < 4; p++)
                wrh[p] = *(const uint2*)(Wh + (size_t)(m0 + aw_m + (p << 5)) * K + k0 + aw_k);
            if (TERMS == 3)
                #pragma unroll
                for (int p = 0; p < 4; p++)
                    wrl[p] = *(const uint2*)(Wl + (size_t)(m0 + aw_m + (p << 5)) * K + k0 + aw_k);
            const float* base; int krel;
            if (k0 < K1) { base = X1b; krel = k0; }
            else         { base = X2b; krel = k0 - K1; }
            #pragma unroll
            for (int p = 0; p < 2; p++)
                xr[p] = *(const float4*)(base + (size_t)(krel + bw_k + (p << 4)) * Nc + n0 + bw_n);
        }

        #pragma unroll
        for (int ks = 0; ks < 2; ks++) {
            const int kk = ks << 4;
            uint32_t ah[2][4], al[2][4], bh[4][2], bl[4][2];
            #pragma unroll
            for (int mf = 0; mf < 2; mf++) {
                const int row = wm * 32 + mf * 16 + a_row;
                const uint32_t off = (uint32_t)(row * A_STRIDE + kk + a_koff) * 2u;
                ldsm_x4(ah_base + off, ah[mf]);
                if (TERMS == 3) ldsm_x4(al_base + off, al[mf]);
            }
            #pragma unroll
            for (int nf = 0; nf < 4; nf++) {
                const int nb = wn * 32 + nf * 8;
                const uint32_t off = (uint32_t)((kk + b_row) * BS + nb) * 2u;
                ldsm_x2t(bh_base + off, bh[nf]);
                if (TERMS >= 2) ldsm_x2t(bl_base + off, bl[nf]);
            }
            #pragma unroll
            for (int mf = 0; mf < 2; mf++)
                #pragma unroll
                for (int nf = 0; nf < 4; nf++) {
                    mma16816(acc[mf][nf], ah[mf], bh[nf]);
                    if (TERMS >= 2) mma16816(acc[mf][nf], ah[mf], bl[nf]);
                    if (TERMS == 3) mma16816(acc[mf][nf], al[mf], bh[nf]);
                }
        }
    }

    const int r = lane >> 2;
    const int c = (lane & 3) << 1;

    #pragma unroll
    for (int mf = 0; mf < 2; mf++) {
        const int gm = m0 + wm * 32 + mf * 16 + r;
        const float bv0 = bias[gm];
        const float bv1 = bias[gm + 8];
        #pragma unroll
        for (int nf = 0; nf < 4; nf++) {
            const int gn = n0 + wn * 32 + nf * 8 + c;
            const size_t i0 = (size_t)gm * Nc + gn;
            const size_t i1 = (size_t)(gm + 8) * Nc + gn;
            if (OUTBF) {
                __nv_bfloat16* Yb = (__nv_bfloat16*)Yv + (size_t)b * M * Nc;
                *(uint32_t*)(Yb + i0) = packbf(acc[mf][nf][0] + bv0, acc[mf][nf][1] + bv0);
                *(uint32_t*)(Yb + i1) = packbf(acc[mf][nf][2] + bv1, acc[mf][nf][3] + bv1);
            } else {
                float* Yb = (float*)Yv + (size_t)b * M * Nc;
                const float* Rb = res ? res + (size_t)b * M * Nc : (const float*)0;
                float2 v0 = make_float2(acc[mf][nf][0] + bv0, acc[mf][nf][1] + bv0);
                float2 v1 = make_float2(acc[mf][nf][2] + bv1, acc[mf][nf][3] + bv1);
                if (Rb) {
                    float2 r0 = *(const float2*)(Rb + i0);
                    float2 r1 = *(const float2*)(Rb + i1);
                    v0.x += r0.x; v0.y += r0.y;
                    v1.x += r1.x; v1.y += r1.y;
                }
                *(float2*)(Yb + i0) = v0;
                *(float2*)(Yb + i1) = v1;
            }
        }
    }
}

// ===========================================================================
// Flash attention (unchanged from R11): bf16 inputs, cp.async KV pipeline.
// ===========================================================================
#define FA_SMEM (17408 + 2*18432)

__global__ void __launch_bounds__(256, 2)
flash_attn(const __nv_bfloat16* __restrict__ q, const __nv_bfloat16* __restrict__ k,
           const __nv_bfloat16* __restrict__ v, float* __restrict__ out)
{
    extern __shared__ __align__(16) char sbuf[];
    const int t = threadIdx.x, lane = t & 31, w = t >> 5;
    const int bh = blockIdx.y, b = bh >> 3, h = bh & 7;
    const int n0 = blockIdx.x * 128;

    const __nv_bfloat16* qb = q + (size_t)b * Cc * NN_ + (size_t)h * NN_;
    const __nv_bfloat16* kb = k + (size_t)b * Cc * NN_ + (size_t)h * NN_;
    const __nv_bfloat16* vb = v + (size_t)b * Cc * NN_ + (size_t)h * NN_;

    __nv_bfloat16* sQh = (__nv_bfloat16*)sbuf;                // [64][136]
    const uint32_t qh_b  = smem_u32(sQh);
    const uint32_t kv0_b = qh_b + 17408;
    const int c_row0 = t >> 3,         c_c0 = (t & 7) << 3;
    const int c_row1 = (t + 256) >> 3, c_c1 = ((t + 256) & 7) << 3;

    {
        const uint32_t kd = kv0_b, vd = kv0_b + 9216;
        cp16(kd + (uint32_t)(c_row0*72 + c_c0)*2u, kb + ((size_t)c_row0 << 14) + c_c0);
        cp16(kd + (uint32_t)(c_row1*72 + c_c1)*2u, kb + ((size_t)c_row1 << 14) + c_c1);
        cp16(vd + (uint32_t)(c_row0*72 + c_c0)*2u, vb + ((size_t)c_row0 << 14) + c_c0);
        cp16(vd + (uint32_t)(c_row1*72 + c_c1)*2u, vb + ((size_t)c_row1 << 14) + c_c1);
        CP_COMMIT();
    }

    {
        const int d = t >> 2, c0 = (t & 3) << 5;
        #pragma unroll
        for (int j = 0; j < 4; j++)
            *(uint4*)&sQh[d*136 + c0 + j*8] = *(const uint4*)(qb + ((size_t)d << 14) + n0 + c0 + j*8);
    }

    float of[8][4] = {};
    float l0 = 0.f, l1 = 0.f;

    const int q_row_off = ((lane>>4)&1)*8 + (lane&7);
    const int q_col = w*16 + ((lane>>3)&1)*8;
    const int brow = ((lane>>3)&1)*8 + (lane&7);
    const int bcol8 = ((lane>>4)&1)*8;
    const int v_row = ((lane>>4)&1)*8 + (lane&7);
    const int v_col = ((lane>>3)&1)*8;

    __syncthreads();

    for (int it = 0; it < NN_/64; it++) {
        const uint32_t cur_b = kv0_b + (uint32_t)(it & 1) * 18432u;
        CP_WAIT0();
        __syncthreads();

        if (it + 1 < NN_/64) {
            const int nx = (it + 1) << 6;
            const uint32_t nb = kv0_b + (uint32_t)((it + 1) & 1) * 18432u;
            const uint32_t kd = nb, vd = nb + 9216;
            cp16(kd + (uint32_t)(c_row0*72 + c_c0)*2u, kb + ((size_t)c_row0 << 14) + nx + c_c0);
            cp16(kd + (uint32_t)(c_row1*72 + c_c1)*2u, kb + ((size_t)c_row1 << 14) + nx + c_c1);
            cp16(vd + (uint32_t)(c_row0*72 + c_c0)*2u, vb + ((size_t)c_row0 << 14) + nx + c_c0);
            cp16(vd + (uint32_t)(c_row1*72 + c_c1)*2u, vb + ((size_t)c_row1 << 14) + nx + c_c1);
            CP_COMMIT();
        }

        const uint32_t kh_b = cur_b;
        const uint32_t vh_b = cur_b + 9216;

        float sf[8][4];
        #pragma unroll
        for (int f = 0; f < 8; f++) { sf[f][0]=0.f; sf[f][1]=0.f; sf[f][2]=0.f; sf[f][3]=0.f; }

        #pragma unroll
        for (int kk = 0; kk < 4; kk++) {
            uint32_t qf[4];
            ldsm_x4t(qh_b + (uint32_t)((kk*16 + q_row_off)*136 + q_col)*2u, qf);
            #pragma unroll
            for (int mp = 0; mp < 4; mp++) {
                const uint32_t koff = (uint32_t)((kk*16 + brow)*72 + mp*16 + bcol8)*2u;
                uint32_t bh4[4];
                ldsm_x4t(kh_b + koff, bh4);
                mma16816(sf[2*mp],   qf, bh4);
                mma16816(sf[2*mp+1], qf, bh4+2);
            }
        }

        float rs0 = 0.f, rs1 = 0.f;
        uint32_t ah4[4][4];
        #pragma unroll
        for (int f = 0; f < 8; f++) {
            float p0 = __expf(0.125f*sf[f][0]);
            float p1 = __expf(0.125f*sf[f][1]);
            float p2 = __expf(0.125f*sf[f][2]);
            float p3 = __expf(0.125f*sf[f][3]);
            rs0 += p0 + p1; rs1 += p2 + p3;
            const int mp = f >> 1, rg = (f & 1) << 1;
            ah4[mp][rg]   = packbf(p0, p1);
            ah4[mp][rg+1] = packbf(p2, p3);
        }
        rs0 += __shfl_xor_sync(0xffffffffu, rs0, 1);
        rs0 += __shfl_xor_sync(0xffffffffu, rs0, 2);
        rs1 += __shfl_xor_sync(0xffffffffu, rs1, 1);
        rs1 += __shfl_xor_sync(0xffffffffu, rs1, 2);
        l0 += rs0;
        l1 += rs1;

        #pragma unroll
        for (int mp = 0; mp < 4; mp++) {
            #pragma unroll
            for (int dp = 0; dp < 4; dp++) {
                const uint32_t voff = (uint32_t)((dp*16 + v_row)*72 + mp*16 + v_col)*2u;
                uint32_t vh4[4];
                ldsm_x4(vh_b + voff, vh4);
                mma16816(of[2*dp],   ah4[mp], vh4);
                mma16816(of[2*dp+1], ah4[mp], vh4+2);
            }
        }
    }

    const float inv0 = 1.f / l0;
    const float inv1 = 1.f / l1;
    float* sO = (float*)(sbuf + 17408);
    float* ob = out + (size_t)b * Cc * NN_ + (size_t)h * NN_;
    __syncthreads();

    #pragma unroll
    for (int half = 0; half < 2; half++) {
        {
            const int r0 = w*16 + (lane >> 2);
            const int dvb = (lane & 3) << 1;
            #pragma unroll
            for (int fl = 0; fl < 4; fl++) {
                const int f = half*4 + fl;
                const int dv = fl*8 + dvb;
                sO[dv*132 + r0]       = of[f][0] * inv0;
                sO[(dv+1)*132 + r0]   = of[f][1] * inv0;
                sO[dv*132 + r0 + 8]   = of[f][2] * inv1;
                sO[(dv+1)*132 + r0+8] = of[f][3] * inv1;
            }
        }
        __syncthreads();
        {
            const int dvl = t >> 3;
            const int nq = (t & 7) << 4;
            #pragma unroll
            for (int j = 0; j < 4; j++) {
                *(float4*)(ob + ((size_t)(half*32 + dvl) << 14) + n0 + nq + 4*j)
                    = *(float4*)&sO[dvl*132 + nq + 4*j];
            }
        }
        __syncthreads();
    }
}

// ===========================================================================
// instance-norm + relu
// ===========================================================================
__global__ void inorm_relu(float* __restrict__ X)
{
    float* row = X + (size_t)blockIdx.x * NN_;
    const int tid = threadIdx.x;
    __shared__ float redA[8], redB[8];

    float v[8];
    float s = 0.f, s2 = 0.f;
    #pragma unroll
    for (int i = 0; i < 8; i++) { v[i] = row[tid + 256*i]; s += v[i]; s2 += v[i]*v[i]; }

    #pragma unroll
    for (int o = 16; o > 0; o >>= 1) {
        s  += __shfl_xor_sync(0xffffffffu, s, o);
        s2 += __shfl_xor_sync(0xffffffffu, s2, o);
    }
    if ((tid & 31) == 0) { redA[tid >> 5] = s; redB[tid >> 5] = s2; }
    __syncthreads();
    if (tid < 8) {
        float a = redA[tid], b = redB[tid];
        #pragma unroll
        for (int o = 4; o > 0; o >>= 1) {
            a += __shfl_xor_sync(0xffu, a, o);
            b += __shfl_xor_sync(0xffu, b, o);
        }
        if (tid == 0) { redA[0] = a; redB[0] = b; }
    }
    __syncthreads();
    const float mean = redA[0] * (1.f / NN_);
    const float var  = redB[0] * (1.f / NN_) - mean * mean;
    const float inv  = rsqrtf(var + 1e-5f);

    #pragma unroll
    for (int i = 0; i < 8; i++) {
        float y = (v[i] - mean) * inv;
        row[tid + 256*i] = y > 0.f ? y : 0.f;
    }
}

// ===========================================================================
// Host side
// ===========================================================================
template<int TERMS, int OUTBF>
static void launch_gemm(const __nv_bfloat16* Wh, const __nv_bfloat16* Wl,
                        const float* bias,
                        const float* X1, const float* X2, int K1,
                        const float* res, void* Y, int M, int K)
{
    dim3 g(NN_ / 64, M / 128, Bb);
    mma_gemm<TERMS, OUTBF><<<g, 256>>>(Wh, Wl, bias, X1, X2, K1, res, Y, M, K, NN_);
}

struct WPtrs {
    __nv_bfloat16 *qh, *kh, *vh, *mh, *w1h, *w1l, *w2h, *w2l;
};

static void run_pass(const float* A, const float* KV, float* dst, const WPtrs& wp,
                     const float* bq, const float* bk, const float* bv, const float* bm,
                     const float* b1, const float* b2,
                     __nv_bfloat16* q, __nv_bfloat16* k, __nv_bfloat16* v,
                     float* att, float* msg, float* hb)
{
    launch_gemm<1,1>(wp.qh, nullptr, bq, A,  nullptr, Cc, nullptr, q, Cc, Cc);
    launch_gemm<1,1>(wp.kh, nullptr, bk, KV, nullptr, Cc, nullptr, k, Cc, Cc);
    launch_gemm<2,1>(wp.vh, nullptr, bv, KV, nullptr, Cc, nullptr, v, Cc, Cc);

    flash_attn<<<dim3(NN_/128, BH), 256, FA_SMEM>>>(q, k, v, att);

    launch_gemm<2,0>(wp.mh, nullptr, bm, att, nullptr, Cc, nullptr, msg, Cc, Cc);

    launch_gemm<3,0>(wp.w1h, wp.w1l, b1, A, msg, Cc, nullptr, hb, 2*Cc, 2*Cc);
    inorm_relu<<<Bb * 2 * Cc, 256>>>(hb);
    launch_gemm<3,0>(wp.w2h, wp.w2l, b2, hb, nullptr, 2*Cc, A, dst, Cc, 2*Cc);
}

extern "C" void kernel_launch(void* const* d_in, const int* in_sizes, int n_in,
                              void* d_out, int out_size)
{
    const float* src = (const float*)d_in[0];
    const float* tgt = (const float*)d_in[1];
    const float* Wq = (const float*)d_in[2];   const float* bq = (const float*)d_in[3];
    const float* Wk = (const float*)d_in[4];   const float* bk = (const float*)d_in[5];
    const float* Wv = (const float*)d_in[6];   const float* bv = (const float*)d_in[7];
    const float* Wm = (const float*)d_in[8];   const float* bm = (const float*)d_in[9];
    const float* W1 = (const float*)d_in[10];  const float* b1 = (const float*)d_in[11];
    const float* W2 = (const float*)d_in[12];  const float* b2 = (const float*)d_in[13];

    float* out = (float*)d_out;
    float* out_src = out;
    float* out_tgt = out + (size_t)BCN;

    static int s_init = 0;
    if (!s_init) {
        cudaFuncSetAttribute(flash_attn, cudaFuncAttributeMaxDynamicSharedMemorySize, FA_SMEM);
        s_init = 1;
    }

    __nv_bfloat16 *q, *k, *v;
    float *att, *msg, *hb;
    cudaGetSymbolAddress((void**)&q,   g_qb);
    cudaGetSymbolAddress((void**)&k,   g_kb);
    cudaGetSymbolAddress((void**)&v,   g_vb);
    cudaGetSymbolAddress((void**)&att, g_att);
    cudaGetSymbolAddress((void**)&msg, g_msg);
    cudaGetSymbolAddress((void**)&hb,  g_h);

    WPtrs wp;
    cudaGetSymbolAddress((void**)&wp.qh,  g_wqh);
    cudaGetSymbolAddress((void**)&wp.kh,  g_wkh);
    cudaGetSymbolAddress((void**)&wp.vh,  g_wvh);
    cudaGetSymbolAddress((void**)&wp.mh,  g_wmh);
    cudaGetSymbolAddress((void**)&wp.w1h, g_w1h);
    cudaGetSymbolAddress((void**)&wp.w1l, g_w1l);
    cudaGetSymbolAddress((void**)&wp.w2h, g_w2h);
    cudaGetSymbolAddress((void**)&wp.w2l, g_w2l);

    // Pre-split weights (hi for all; lo for the TERMS=3 pair)
    {
        const int n512 = Cc*Cc/4;      // 65536 float4
        wsplit<<<n512/256, 256>>>(Wq, wp.qh, nullptr, n512);
        wsplit<<<n512/256, 256>>>(Wk, wp.kh, nullptr, n512);
        wsplit<<<n512/256, 256>>>(Wv, wp.vh, nullptr, n512);
        wsplit<<<n512/256, 256>>>(Wm, wp.mh, nullptr, n512);
        wsplit<<<4*n512/256, 256>>>(W1, wp.w1h, wp.w1l, 4*n512);
        wsplit<<<2*n512/256, 256>>>(W2, wp.w2h, wp.w2l, 2*n512);
    }

    run_pass(src, tgt, out_src, wp, bq, bk, bv, bm, b1, b2, q, k, v, att, msg, hb);
    run_pass(tgt, out_src, out_tgt, wp, bq, bk, bv, bm, b1, b2, q, k, v, att, msg, hb);
}

// round 17
// speedup vs baseline: 1.2809x; 1.0202x over previous
#include <cuda_runtime.h>
#include <cuda_bf16.h>
#include <cstdint>
#include <math.h>

// Problem constants
#define Bb 4
#define Cc 512
#define NN_ 2048
#define Hh 8
#define Dd 64
#define BH (Bb*Hh)
#define BCN (Bb*Cc*NN_)

// Scratch
__device__ __nv_bfloat16 g_qb[BCN];
__device__ __nv_bfloat16 g_kb[BCN];
__device__ __nv_bfloat16 g_vb[BCN];
__device__ float g_att[BCN];
__device__ float g_msg[BCN];
__device__ float g_h[2*BCN];

// Pre-split weights (bf16)
__device__ __nv_bfloat16 g_wqh[Cc*Cc];
__device__ __nv_bfloat16 g_wkh[Cc*Cc];
__device__ __nv_bfloat16 g_wvh[Cc*Cc];
__device__ __nv_bfloat16 g_wmh[Cc*Cc];
__device__ __nv_bfloat16 g_w1h[4*Cc*Cc];
__device__ __nv_bfloat16 g_w1l[4*Cc*Cc];
__device__ __nv_bfloat16 g_w2h[2*Cc*Cc];
__device__ __nv_bfloat16 g_w2l[2*Cc*Cc];

// ===========================================================================
// Warp-level MMA helpers
// ===========================================================================
__device__ __forceinline__ uint32_t smem_u32(const void* p){
    uint32_t a;
    asm("{ .reg .u64 t; cvta.to.shared.u64 t, %1; cvt.u32.u64 %0, t; }" : "=r"(a) : "l"(p));
    return a;
}
__device__ __forceinline__ void ldsm_x4(uint32_t addr, uint32_t* r){
    asm volatile("ldmatrix.sync.aligned.m8n8.x4.shared.b16 {%0,%1,%2,%3}, [%4];"
        : "=r"(r[0]), "=r"(r[1]), "=r"(r[2]), "=r"(r[3]) : "r"(addr));
}
__device__ __forceinline__ void ldsm_x4t(uint32_t addr, uint32_t* r){
    asm volatile("ldmatrix.sync.aligned.m8n8.x4.trans.shared.b16 {%0,%1,%2,%3}, [%4];"
        : "=r"(r[0]), "=r"(r[1]), "=r"(r[2]), "=r"(r[3]) : "r"(addr));
}
__device__ __forceinline__ void ldsm_x2t(uint32_t addr, uint32_t* r){
    asm volatile("ldmatrix.sync.aligned.m8n8.x2.trans.shared.b16 {%0,%1}, [%2];"
        : "=r"(r[0]), "=r"(r[1]) : "r"(addr));
}
__device__ __forceinline__ void mma16816(float* c, const uint32_t* a, const uint32_t* b){
    asm volatile("mma.sync.aligned.m16n8k16.row.col.f32.bf16.bf16.f32 "
        "{%0,%1,%2,%3}, {%4,%5,%6,%7}, {%8,%9}, {%0,%1,%2,%3};"
        : "+f"(c[0]), "+f"(c[1]), "+f"(c[2]), "+f"(c[3])
        : "r"(a[0]), "r"(a[1]), "r"(a[2]), "r"(a[3]), "r"(b[0]), "r"(b[1]));
}
__device__ __forceinline__ void cp16(uint32_t dst, const void* src){
    asm volatile("cp.async.ca.shared.global [%0], [%1], 16;" :: "r"(dst), "l"(src));
}
#define CP_COMMIT() asm volatile("cp.async.commit_group;" ::: "memory")
#define CP_WAIT0()  asm volatile("cp.async.wait_group 0;" ::: "memory")

__device__ __forceinline__ void split4(float4 v, uint2& H, uint2& L)
{
    __nv_bfloat16 h0 = __float2bfloat16(v.x);
    __nv_bfloat16 h1 = __float2bfloat16(v.y);
    __nv_bfloat16 h2 = __float2bfloat16(v.z);
    __nv_bfloat16 h3 = __float2bfloat16(v.w);
    __nv_bfloat16 l0 = __float2bfloat16(v.x - __bfloat162float(h0));
    __nv_bfloat16 l1 = __float2bfloat16(v.y - __bfloat162float(h1));
    __nv_bfloat16 l2 = __float2bfloat16(v.z - __bfloat162float(h2));
    __nv_bfloat16 l3 = __float2bfloat16(v.w - __bfloat162float(h3));
    H.x = (uint32_t)__bfloat16_as_ushort(h0) | ((uint32_t)__bfloat16_as_ushort(h1) << 16);
    H.y = (uint32_t)__bfloat16_as_ushort(h2) | ((uint32_t)__bfloat16_as_ushort(h3) << 16);
    L.x = (uint32_t)__bfloat16_as_ushort(l0) | ((uint32_t)__bfloat16_as_ushort(l1) << 16);
    L.y = (uint32_t)__bfloat16_as_ushort(l2) | ((uint32_t)__bfloat16_as_ushort(l3) << 16);
}

__device__ __forceinline__ void hi4(float4 v, uint2& H)
{
    __nv_bfloat16 h0 = __float2bfloat16(v.x);
    __nv_bfloat16 h1 = __float2bfloat16(v.y);
    __nv_bfloat16 h2 = __float2bfloat16(v.z);
    __nv_bfloat16 h3 = __float2bfloat16(v.w);
    H.x = (uint32_t)__bfloat16_as_ushort(h0) | ((uint32_t)__bfloat16_as_ushort(h1) << 16);
    H.y = (uint32_t)__bfloat16_as_ushort(h2) | ((uint32_t)__bfloat16_as_ushort(h3) << 16);
}

__device__ __forceinline__ uint32_t packbf(float a, float b){
    __nv_bfloat162 t = __floats2bfloat162_rn(a, b);
    return *(uint32_t*)&t;
}

// ===========================================================================
// Weight pre-split: fp32 -> bf16 hi (+ optional lo)
// ===========================================================================
__global__ void wsplit(const float* __restrict__ W, __nv_bfloat16* __restrict__ H,
                       __nv_bfloat16* __restrict__ L, int n4)
{
    int i = blockIdx.x * blockDim.x + threadIdx.x;
    if (i < n4) {
        float4 v = ((const float4*)W)[i];
        uint2 Hv, Lv; split4(v, Hv, Lv);
        *(uint2*)(H + 4*(size_t)i) = Hv;
        if (L) *(uint2*)(L + 4*(size_t)i) = Lv;
    }
}

// ===========================================================================
// MMA GEMM: 128m x 64n, 2 CTAs/SM, DOUBLE-BUFFERED (1 sync/chunk).
// A via cp.async from pre-split bf16 weights; B via reg-prefetch + split STS.
// TERMS=3: AhBh + AhBl + AlBh ; TERMS=2: AhBh + AhBl ; TERMS=1: AhBh.
// Dyn smem: Ah[2][128*40] @0; Al[2][...] @20480 (T3); Bh[2][32*72] @B_OFF;
//           Bl[2][32*72] @B_OFF+9216 (T>=2).
// ===========================================================================
#define A_STRIDE 40
#define BS 72

template<int TERMS>
__host__ __device__ constexpr int gemm_smem(){
    return (TERMS == 3 ? 40960 : 20480) + (TERMS >= 2 ? 18432 : 9216);
}

template<int TERMS, int OUTBF>
__global__ void __launch_bounds__(256, 2)
mma_gemm(const __nv_bfloat16* __restrict__ Wh, const __nv_bfloat16* __restrict__ Wl,
         const float* __restrict__ bias,
         const float* __restrict__ X1, const float* __restrict__ X2, int K1,
         const float* __restrict__ res, void* __restrict__ Yv,
         int M, int K, int Nc)
{
    extern __shared__ __align__(16) char gsm[];
    const uint32_t sm0 = smem_u32(gsm);
    const uint32_t AL_OFF = 20480u;
    const uint32_t B_OFF  = (TERMS == 3) ? 40960u : 20480u;
    const uint32_t BL_OFF = B_OFF + 9216u;

    const int t = threadIdx.x;
    const int lane = t & 31;
    const int wid = t >> 5;
    const int wm = wid & 3;
    const int wn = wid >> 2;

    const int b  = blockIdx.z;
    const int m0 = blockIdx.y * 128;
    const int n0 = blockIdx.x * 64;
    const float* X1b = X1 + (size_t)b * K1 * Nc;
    const float* X2b = X2 ? X2 + (size_t)b * (K - K1) * Nc : (const float*)0;

    float acc[2][4][4] = {};

    const int a_row = (lane & 15);
    const int a_koff = (lane & 16) ? 8 : 0;
    const int b_row = (lane & 15);

    // A cp.async coords: two rows per thread (ar, ar+64), one 16B seg each
    const int ar = t >> 2;
    const int aseg = (t & 3);
    // B staging coords
    const int bw_k = (t >> 4);
    const int bw_n = (t & 15) << 2;

    float4 xr[2];

    // prologue: cp.async A chunk0 -> buf0; prefetch B chunk0
    {
        cp16(sm0 + (uint32_t)(ar*80 + aseg*16),
             Wh + (size_t)(m0 + ar) * K + aseg*8);
        cp16(sm0 + (uint32_t)((ar+64)*80 + aseg*16),
             Wh + (size_t)(m0 + ar + 64) * K + aseg*8);
        if (TERMS == 3) {
            cp16(sm0 + AL_OFF + (uint32_t)(ar*80 + aseg*16),
                 Wl + (size_t)(m0 + ar) * K + aseg*8);
            cp16(sm0 + AL_OFF + (uint32_t)((ar+64)*80 + aseg*16),
                 Wl + (size_t)(m0 + ar + 64) * K + aseg*8);
        }
        CP_COMMIT();
    }
    #pragma unroll
    for (int p = 0; p < 2; p++)
        xr[p] = *(const float4*)(X1b + (size_t)(bw_k + (p << 4)) * Nc + n0 + bw_n);

    const int nchunks = K >> 5;
    for (int ch = 0; ch < nchunks; ch++) {
        const int cur = ch & 1;
        const uint32_t abuf  = sm0 + (uint32_t)cur * 10240u;
        const uint32_t albuf = sm0 + AL_OFF + (uint32_t)cur * 10240u;
        const uint32_t bbuf  = sm0 + B_OFF  + (uint32_t)cur * 4608u;
        const uint32_t blbuf = sm0 + BL_OFF + (uint32_t)cur * 4608u;
        char* bhp = gsm + (B_OFF  + (uint32_t)cur * 4608u);
        char* blp = gsm + (BL_OFF + (uint32_t)cur * 4608u);

        // STS B chunk ch (from prefetched registers)
        #pragma unroll
        for (int p = 0; p < 2; p++) {
            const uint32_t soff = (uint32_t)((bw_k + (p << 4)) * BS + bw_n) * 2u;
            if (TERMS >= 2) {
                uint2 Hv, Lv; split4(xr[p], Hv, Lv);
                *(uint2*)(bhp + soff) = Hv;
                *(uint2*)(blp + soff) = Lv;
            } else {
                uint2 Hv; hi4(xr[p], Hv);
                *(uint2*)(bhp + soff) = Hv;
            }
        }

        CP_WAIT0();          // A[ch] arrived (only group in flight)
        __syncthreads();     // all staging visible; prev MMAs done

        // issue next chunk's A copy + B prefetch (lands during MMA below)
        if (ch + 1 < nchunks) {
            const int k0 = (ch + 1) << 5;
            const uint32_t nab  = sm0 + (uint32_t)(cur ^ 1) * 10240u;
            const uint32_t nalb = sm0 + AL_OFF + (uint32_t)(cur ^ 1) * 10240u;
            cp16(nab + (uint32_t)(ar*80 + aseg*16),
                 Wh + (size_t)(m0 + ar) * K + k0 + aseg*8);
            cp16(nab + (uint32_t)((ar+64)*80 + aseg*16),
                 Wh + (size_t)(m0 + ar + 64) * K + k0 + aseg*8);
            if (TERMS == 3) {
                cp16(nalb + (uint32_t)(ar*80 + aseg*16),
                     Wl + (size_t)(m0 + ar) * K + k0 + aseg*8);
                cp16(nalb + (uint32_t)((ar+64)*80 + aseg*16),
                     Wl + (size_t)(m0 + ar + 64) * K + k0 + aseg*8);
            }
            CP_COMMIT();
            const float* base; int krel;
            if (k0 < K1) { base = X1b; krel = k0; }
            else         { base = X2b; krel = k0 - K1; }
            #pragma unroll
            for (int p = 0; p < 2; p++)
                xr[p] = *(const float4*)(base + (size_t)(krel + bw_k + (p << 4)) * Nc + n0 + bw_n);
        }

        // MMA on current buffers
        #pragma unroll
        for (int ks = 0; ks < 2; ks++) {
            const int kk = ks << 4;
            uint32_t ah[2][4], al[2][4], bh[4][2], bl[4][2];
            #pragma unroll
            for (int mf = 0; mf < 2; mf++) {
                const int row = wm * 32 + mf * 16 + a_row;
                const uint32_t off = (uint32_t)(row * A_STRIDE + kk + a_koff) * 2u;
                ldsm_x4(abuf + off, ah[mf]);
                if (TERMS == 3) ldsm_x4(albuf + off, al[mf]);
            }
            #pragma unroll
            for (int nf = 0; nf < 4; nf++) {
                const int nb = wn * 32 + nf * 8;
                const uint32_t off = (uint32_t)((kk + b_row) * BS + nb) * 2u;
                ldsm_x2t(bbuf + off, bh[nf]);
                if (TERMS >= 2) ldsm_x2t(blbuf + off, bl[nf]);
            }
            #pragma unroll
            for (int mf = 0; mf < 2; mf++)
                #pragma unroll
                for (int nf = 0; nf < 4; nf++) {
                    mma16816(acc[mf][nf], ah[mf], bh[nf]);
                    if (TERMS >= 2) mma16816(acc[mf][nf], ah[mf], bl[nf]);
                    if (TERMS == 3) mma16816(acc[mf][nf], al[mf], bh[nf]);
                }
        }
    }

    const int r = lane >> 2;
    const int c = (lane & 3) << 1;

    #pragma unroll
    for (int mf = 0; mf < 2; mf++) {
        const int gm = m0 + wm * 32 + mf * 16 + r;
        const float bv0 = bias[gm];
        const float bv1 = bias[gm + 8];
        #pragma unroll
        for (int nf = 0; nf < 4; nf++) {
            const int gn = n0 + wn * 32 + nf * 8 + c;
            const size_t i0 = (size_t)gm * Nc + gn;
            const size_t i1 = (size_t)(gm + 8) * Nc + gn;
            if (OUTBF) {
                __nv_bfloat16* Yb = (__nv_bfloat16*)Yv + (size_t)b * M * Nc;
                *(uint32_t*)(Yb + i0) = packbf(acc[mf][nf][0] + bv0, acc[mf][nf][1] + bv0);
                *(uint32_t*)(Yb + i1) = packbf(acc[mf][nf][2] + bv1, acc[mf][nf][3] + bv1);
            } else {
                float* Yb = (float*)Yv + (size_t)b * M * Nc;
                const float* Rb = res ? res + (size_t)b * M * Nc : (const float*)0;
                float2 v0 = make_float2(acc[mf][nf][0] + bv0, acc[mf][nf][1] + bv0);
                float2 v1 = make_float2(acc[mf][nf][2] + bv1, acc[mf][nf][3] + bv1);
                if (Rb) {
                    float2 r0 = *(const float2*)(Rb + i0);
                    float2 r1 = *(const float2*)(Rb + i1);
                    v0.x += r0.x; v0.y += r0.y;
                    v1.x += r1.x; v1.y += r1.y;
                }
                *(float2*)(Yb + i0) = v0;
                *(float2*)(Yb + i1) = v1;
            }
        }
    }
}

// ===========================================================================
// Flash attention (unchanged from R11): bf16 inputs, cp.async KV pipeline.
// ===========================================================================
#define FA_SMEM (17408 + 2*18432)

__global__ void __launch_bounds__(256, 2)
flash_attn(const __nv_bfloat16* __restrict__ q, const __nv_bfloat16* __restrict__ k,
           const __nv_bfloat16* __restrict__ v, float* __restrict__ out)
{
    extern __shared__ __align__(16) char sbuf[];
    const int t = threadIdx.x, lane = t & 31, w = t >> 5;
    const int bh = blockIdx.y, b = bh >> 3, h = bh & 7;
    const int n0 = blockIdx.x * 128;

    const __nv_bfloat16* qb = q + (size_t)b * Cc * NN_ + (size_t)h * NN_;
    const __nv_bfloat16* kb = k + (size_t)b * Cc * NN_ + (size_t)h * NN_;
    const __nv_bfloat16* vb = v + (size_t)b * Cc * NN_ + (size_t)h * NN_;

    __nv_bfloat16* sQh = (__nv_bfloat16*)sbuf;                // [64][136]
    const uint32_t qh_b  = smem_u32(sQh);
    const uint32_t kv0_b = qh_b + 17408;
    const int c_row0 = t >> 3,         c_c0 = (t & 7) << 3;
    const int c_row1 = (t + 256) >> 3, c_c1 = ((t + 256) & 7) << 3;

    {
        const uint32_t kd = kv0_b, vd = kv0_b + 9216;
        cp16(kd + (uint32_t)(c_row0*72 + c_c0)*2u, kb + ((size_t)c_row0 << 14) + c_c0);
        cp16(kd + (uint32_t)(c_row1*72 + c_c1)*2u, kb + ((size_t)c_row1 << 14) + c_c1);
        cp16(vd + (uint32_t)(c_row0*72 + c_c0)*2u, vb + ((size_t)c_row0 << 14) + c_c0);
        cp16(vd + (uint32_t)(c_row1*72 + c_c1)*2u, vb + ((size_t)c_row1 << 14) + c_c1);
        CP_COMMIT();
    }

    {
        const int d = t >> 2, c0 = (t & 3) << 5;
        #pragma unroll
        for (int j = 0; j < 4; j++)
            *(uint4*)&sQh[d*136 + c0 + j*8] = *(const uint4*)(qb + ((size_t)d << 14) + n0 + c0 + j*8);
    }

    float of[8][4] = {};
    float l0 = 0.f, l1 = 0.f;

    const int q_row_off = ((lane>>4)&1)*8 + (lane&7);
    const int q_col = w*16 + ((lane>>3)&1)*8;
    const int brow = ((lane>>3)&1)*8 + (lane&7);
    const int bcol8 = ((lane>>4)&1)*8;
    const int v_row = ((lane>>4)&1)*8 + (lane&7);
    const int v_col = ((lane>>3)&1)*8;

    __syncthreads();

    for (int it = 0; it < NN_/64; it++) {
        const uint32_t cur_b = kv0_b + (uint32_t)(it & 1) * 18432u;
        CP_WAIT0();
        __syncthreads();

        if (it + 1 < NN_/64) {
            const int nx = (it + 1) << 6;
            const uint32_t nb = kv0_b + (uint32_t)((it + 1) & 1) * 18432u;
            const uint32_t kd = nb, vd = nb + 9216;
            cp16(kd + (uint32_t)(c_row0*72 + c_c0)*2u, kb + ((size_t)c_row0 << 14) + nx + c_c0);
            cp16(kd + (uint32_t)(c_row1*72 + c_c1)*2u, kb + ((size_t)c_row1 << 14) + nx + c_c1);
            cp16(vd + (uint32_t)(c_row0*72 + c_c0)*2u, vb + ((size_t)c_row0 << 14) + nx + c_c0);
            cp16(vd + (uint32_t)(c_row1*72 + c_c1)*2u, vb + ((size_t)c_row1 << 14) + nx + c_c1);
            CP_COMMIT();
        }

        const uint32_t kh_b = cur_b;
        const uint32_t vh_b = cur_b + 9216;

        float sf[8][4];
        #pragma unroll
        for (int f = 0; f < 8; f++) { sf[f][0]=0.f; sf[f][1]=0.f; sf[f][2]=0.f; sf[f][3]=0.f; }

        #pragma unroll
        for (int kk = 0; kk < 4; kk++) {
            uint32_t qf[4];
            ldsm_x4t(qh_b + (uint32_t)((kk*16 + q_row_off)*136 + q_col)*2u, qf);
            #pragma unroll
            for (int mp = 0; mp < 4; mp++) {
                const uint32_t koff = (uint32_t)((kk*16 + brow)*72 + mp*16 + bcol8)*2u;
                uint32_t bh4[4];
                ldsm_x4t(kh_b + koff, bh4);
                mma16816(sf[2*mp],   qf, bh4);
                mma16816(sf[2*mp+1], qf, bh4+2);
            }
        }

        float rs0 = 0.f, rs1 = 0.f;
        uint32_t ah4[4][4];
        #pragma unroll
        for (int f = 0; f < 8; f++) {
            float p0 = __expf(0.125f*sf[f][0]);
            float p1 = __expf(0.125f*sf[f][1]);
            float p2 = __expf(0.125f*sf[f][2]);
            float p3 = __expf(0.125f*sf[f][3]);
            rs0 += p0 + p1; rs1 += p2 + p3;
            const int mp = f >> 1, rg = (f & 1) << 1;
            ah4[mp][rg]   = packbf(p0, p1);
            ah4[mp][rg+1] = packbf(p2, p3);
        }
        rs0 += __shfl_xor_sync(0xffffffffu, rs0, 1);
        rs0 += __shfl_xor_sync(0xffffffffu, rs0, 2);
        rs1 += __shfl_xor_sync(0xffffffffu, rs1, 1);
        rs1 += __shfl_xor_sync(0xffffffffu, rs1, 2);
        l0 += rs0;
        l1 += rs1;

        #pragma unroll
        for (int mp = 0; mp < 4; mp++) {
            #pragma unroll
            for (int dp = 0; dp < 4; dp++) {
                const uint32_t voff = (uint32_t)((dp*16 + v_row)*72 + mp*16 + v_col)*2u;
                uint32_t vh4[4];
                ldsm_x4(vh_b + voff, vh4);
                mma16816(of[2*dp],   ah4[mp], vh4);
                mma16816(of[2*dp+1], ah4[mp], vh4+2);
            }
        }
    }

    const float inv0 = 1.f / l0;
    const float inv1 = 1.f / l1;
    float* sO = (float*)(sbuf + 17408);
    float* ob = out + (size_t)b * Cc * NN_ + (size_t)h * NN_;
    __syncthreads();

    #pragma unroll
    for (int half = 0; half < 2; half++) {
        {
            const int r0 = w*16 + (lane >> 2);
            const int dvb = (lane & 3) << 1;
            #pragma unroll
            for (int fl = 0; fl < 4; fl++) {
                const int f = half*4 + fl;
                const int dv = fl*8 + dvb;
                sO[dv*132 + r0]       = of[f][0] * inv0;
                sO[(dv+1)*132 + r0]   = of[f][1] * inv0;
                sO[dv*132 + r0 + 8]   = of[f][2] * inv1;
                sO[(dv+1)*132 + r0+8] = of[f][3] * inv1;
            }
        }
        __syncthreads();
        {
            const int dvl = t >> 3;
            const int nq = (t & 7) << 4;
            #pragma unroll
            for (int j = 0; j < 4; j++) {
                *(float4*)(ob + ((size_t)(half*32 + dvl) << 14) + n0 + nq + 4*j)
                    = *(float4*)&sO[dvl*132 + nq + 4*j];
            }
        }
        __syncthreads();
    }
}

// ===========================================================================
// instance-norm + relu
// ===========================================================================
__global__ void inorm_relu(float* __restrict__ X)
{
    float* row = X + (size_t)blockIdx.x * NN_;
    const int tid = threadIdx.x;
    __shared__ float redA[8], redB[8];

    float v[8];
    float s = 0.f, s2 = 0.f;
    #pragma unroll
    for (int i = 0; i < 8; i++) { v[i] = row[tid + 256*i]; s += v[i]; s2 += v[i]*v[i]; }

    #pragma unroll
    for (int o = 16; o > 0; o >>= 1) {
        s  += __shfl_xor_sync(0xffffffffu, s, o);
        s2 += __shfl_xor_sync(0xffffffffu, s2, o);
    }
    if ((tid & 31) == 0) { redA[tid >> 5] = s; redB[tid >> 5] = s2; }
    __syncthreads();
    if (tid < 8) {
        float a = redA[tid], b = redB[tid];
        #pragma unroll
        for (int o = 4; o > 0; o >>= 1) {
            a += __shfl_xor_sync(0xffu, a, o);
            b += __shfl_xor_sync(0xffu, b, o);
        }
        if (tid == 0) { redA[0] = a; redB[0] = b; }
    }
    __syncthreads();
    const float mean = redA[0] * (1.f / NN_);
    const float var  = redB[0] * (1.f / NN_) - mean * mean;
    const float inv  = rsqrtf(var + 1e-5f);

    #pragma unroll
    for (int i = 0; i < 8; i++) {
        float y = (v[i] - mean) * inv;
        row[tid + 256*i] = y > 0.f ? y : 0.f;
    }
}

// ===========================================================================
// Host side
// ===========================================================================
template<int TERMS, int OUTBF>
static void launch_gemm(const __nv_bfloat16* Wh, const __nv_bfloat16* Wl,
                        const float* bias,
                        const float* X1, const float* X2, int K1,
                        const float* res, void* Y, int M, int K)
{
    dim3 g(NN_ / 64, M / 128, Bb);
    mma_gemm<TERMS, OUTBF><<<g, 256, gemm_smem<TERMS>()>>>(Wh, Wl, bias, X1, X2, K1, res, Y, M, K, NN_);
}

struct WPtrs {
    __nv_bfloat16 *qh, *kh, *vh, *mh, *w1h, *w1l, *w2h, *w2l;
};

static void run_pass(const float* A, const float* KV, float* dst, const WPtrs& wp,
                     const float* bq, const float* bk, const float* bv, const float* bm,
                     const float* b1, const float* b2,
                     __nv_bfloat16* q, __nv_bfloat16* k, __nv_bfloat16* v,
                     float* att, float* msg, float* hb)
{
    launch_gemm<1,1>(wp.qh, nullptr, bq, A,  nullptr, Cc, nullptr, q, Cc, Cc);
    launch_gemm<1,1>(wp.kh, nullptr, bk, KV, nullptr, Cc, nullptr, k, Cc, Cc);
    launch_gemm<2,1>(wp.vh, nullptr, bv, KV, nullptr, Cc, nullptr, v, Cc, Cc);

    flash_attn<<<dim3(NN_/128, BH), 256, FA_SMEM>>>(q, k, v, att);

    launch_gemm<2,0>(wp.mh, nullptr, bm, att, nullptr, Cc, nullptr, msg, Cc, Cc);

    launch_gemm<3,0>(wp.w1h, wp.w1l, b1, A, msg, Cc, nullptr, hb, 2*Cc, 2*Cc);
    inorm_relu<<<Bb * 2 * Cc, 256>>>(hb);
    launch_gemm<3,0>(wp.w2h, wp.w2l, b2, hb, nullptr, 2*Cc, A, dst, Cc, 2*Cc);
}

extern "C" void kernel_launch(void* const* d_in, const int* in_sizes, int n_in,
                              void* d_out, int out_size)
{
    const float* src = (const float*)d_in[0];
    const float* tgt = (const float*)d_in[1];
    const float* Wq = (const float*)d_in[2];   const float* bq = (const float*)d_in[3];
    const float* Wk = (const float*)d_in[4];   const float* bk = (const float*)d_in[5];
    const float* Wv = (const float*)d_in[6];   const float* bv = (const float*)d_in[7];
    const float* Wm = (const float*)d_in[8];   const float* bm = (const float*)d_in[9];
    const float* W1 = (const float*)d_in[10];  const float* b1 = (const float*)d_in[11];
    const float* W2 = (const float*)d_in[12];  const float* b2 = (const float*)d_in[13];

    float* out = (float*)d_out;
    float* out_src = out;
    float* out_tgt = out + (size_t)BCN;

    static int s_init = 0;
    if (!s_init) {
        cudaFuncSetAttribute(flash_attn, cudaFuncAttributeMaxDynamicSharedMemorySize, FA_SMEM);
        cudaFuncSetAttribute(mma_gemm<1,1>, cudaFuncAttributeMaxDynamicSharedMemorySize, gemm_smem<1>());
        cudaFuncSetAttribute(mma_gemm<2,1>, cudaFuncAttributeMaxDynamicSharedMemorySize, gemm_smem<2>());
        cudaFuncSetAttribute(mma_gemm<2,0>, cudaFuncAttributeMaxDynamicSharedMemorySize, gemm_smem<2>());
        cudaFuncSetAttribute(mma_gemm<3,0>, cudaFuncAttributeMaxDynamicSharedMemorySize, gemm_smem<3>());
        s_init = 1;
    }

    __nv_bfloat16 *q, *k, *v;
    float *att, *msg, *hb;
    cudaGetSymbolAddress((void**)&q,   g_qb);
    cudaGetSymbolAddress((void**)&k,   g_kb);
    cudaGetSymbolAddress((void**)&v,   g_vb);
    cudaGetSymbolAddress((void**)&att, g_att);
    cudaGetSymbolAddress((void**)&msg, g_msg);
    cudaGetSymbolAddress((void**)&hb,  g_h);

    WPtrs wp;
    cudaGetSymbolAddress((void**)&wp.qh,  g_wqh);
    cudaGetSymbolAddress((void**)&wp.kh,  g_wkh);
    cudaGetSymbolAddress((void**)&wp.vh,  g_wvh);
    cudaGetSymbolAddress((void**)&wp.mh,  g_wmh);
    cudaGetSymbolAddress((void**)&wp.w1h, g_w1h);
    cudaGetSymbolAddress((void**)&wp.w1l, g_w1l);
    cudaGetSymbolAddress((void**)&wp.w2h, g_w2h);
    cudaGetSymbolAddress((void**)&wp.w2l, g_w2l);

    // Pre-split weights (hi for all; lo for the TERMS=3 pair)
    {
        const int n512 = Cc*Cc/4;      // 65536 float4
        wsplit<<<n512/256, 256>>>(Wq, wp.qh, nullptr, n512);
        wsplit<<<n512/256, 256>>>(Wk, wp.kh, nullptr, n512);
        wsplit<<<n512/256, 256>>>(Wv, wp.vh, nullptr, n512);
        wsplit<<<n512/256, 256>>>(Wm, wp.mh, nullptr, n512);
        wsplit<<<4*n512/256, 256>>>(W1, wp.w1h, wp.w1l, 4*n512);
        wsplit<<<2*n512/256, 256>>>(W2, wp.w2h, wp.w2l, 2*n512);
    }

    run_pass(src, tgt, out_src, wp, bq, bk, bv, bm, b1, b2, q, k, v, att, msg, hb);
    run_pass(tgt, out_src, out_tgt, wp, bq, bk, bv, bm, b1, b2, q, k, v, att, msg, hb);
}